// round 2
// baseline (speedup 1.0000x reference)
#include <cuda_runtime.h>

// NAM_42442866819214 — single fused kernel.
//
// Math collapse (valid per-feature when b1[f,:]==0 and b2[f,:]==0, verified
// at runtime into g_mode[f]):
//   relu(x*w) = x * (x>0 ? max(w,0) : min(w,0))
//   contrib(b,f) = x * (x>0 ? dpos[f] : dneg[f]) + b3[f]
// where dpos/dneg fold W1,W2,W3 into 2 scalars per feature.
//
// Single-kernel structure (graph-replay deterministic):
//   blocks 0..15 : precompute dpos/dneg/mode for 8 features each, then
//                  release via g_ready counter
//   all blocks   : spin on g_ready, then stream the main phase
//                  (1 warp per batch row, float4 I/O, shuffle reduction)
//   last block   : resets g_ready/g_done to 0 (state identical across replays)

#define NB   8192
#define NF   128
#define NH1  64
#define NH2  32
#define GRID 256          // NB / ROWS_PER_BLOCK
#define ROWS_PER_BLOCK 32 // 4 warps * 8 iters
#define PRE_BLOCKS 16     // 8 features per precompute block

__device__ float g_dpos[NF];
__device__ float g_dneg[NF];
__device__ int   g_mode[NF];   // 0 = fast path valid
__device__ int   g_ready;      // zero-init; reset to 0 at kernel end
__device__ int   g_done;       // zero-init; reset to 0 at kernel end

// Full per-element MLP (dead path unless biases are nonzero; keeps the
// kernel correct for arbitrary b1/b2).
__device__ __noinline__ float mlp_full(float x, int f,
                                       const float* __restrict__ W1,
                                       const float* __restrict__ b1,
                                       const float* __restrict__ W2,
                                       const float* __restrict__ b2,
                                       const float* __restrict__ W3) {
    float acc = 0.f;
    for (int k = 0; k < NH2; k++) {
        float a = b2[f * NH2 + k];
        for (int i = 0; i < NH1; i++) {
            float h1 = fmaxf(fmaf(x, W1[f * NH1 + i], b1[f * NH1 + i]), 0.f);
            a = fmaf(h1, W2[(f * NH1 + i) * NH2 + k], a);
        }
        acc = fmaf(fmaxf(a, 0.f), W3[f * NH2 + k], acc);
    }
    return acc;
}

__global__ void __launch_bounds__(NF)
nam_fused(const float* __restrict__ inputs,
          const float* __restrict__ W1,
          const float* __restrict__ b1,
          const float* __restrict__ W2,
          const float* __restrict__ b2,
          const float* __restrict__ W3,
          const float* __restrict__ b3,
          const float* __restrict__ bias,
          float* __restrict__ out) {
    const int tid  = threadIdx.x;
    const int lane = tid & 31;
    const int warp = tid >> 5;   // 0..3

    // ---- Phase 1: precompute (blocks 0..15) -----------------------------
    if (blockIdx.x < PRE_BLOCKS) {
        const int k = lane;  // H2 unit
#pragma unroll
        for (int g = 0; g < 2; g++) {
            const int f = blockIdx.x * 8 + g * 4 + warp;  // one feature per warp
            int nz = (b1[f * NH1 + k]      != 0.f) |
                     (b1[f * NH1 + 32 + k] != 0.f) |
                     (b2[f * NH2 + k]      != 0.f);
            unsigned bal = __ballot_sync(0xffffffffu, nz);

            float cp = 0.f, cn = 0.f;
#pragma unroll
            for (int i = 0; i < NH1; i++) {
                float w  = W1[f * NH1 + i];                 // warp-uniform
                float w2 = W2[(f * NH1 + i) * NH2 + k];     // coalesced
                cp = fmaf(w2, fmaxf(w, 0.f), cp);
                cn = fmaf(w2, fminf(w, 0.f), cn);
            }
            float w3 = W3[f * NH2 + k];
            float dp = w3 * fmaxf(cp, 0.f);
            float dn = w3 * fminf(cn, 0.f);
#pragma unroll
            for (int o = 16; o > 0; o >>= 1) {
                dp += __shfl_xor_sync(0xffffffffu, dp, o);
                dn += __shfl_xor_sync(0xffffffffu, dn, o);
            }
            if (lane == 0) {
                g_dpos[f] = dp;
                g_dneg[f] = dn;
                g_mode[f] = bal ? 1 : 0;
            }
        }
        __syncthreads();
        if (tid == 0) {
            __threadfence();
            atomicAdd(&g_ready, 1);
        }
    }

    // ---- Spin until precompute is published ------------------------------
    if (tid == 0) {
        while (atomicAdd(&g_ready, 0) < PRE_BLOCKS) { __nanosleep(64); }
    }
    __syncthreads();
    __threadfence();

    // ---- Phase 2: streaming main (all 256 blocks) ------------------------
    // Warp w of block B handles rows {B*32 + it*4 + w : it in 0..7}.
    // Lane l owns features 4l..4l+3 (float4 I/O).
    const float4* in4 = (const float4*)inputs;
    float4*       c4  = (float4*)(out + NB);

    const float4 dp4 = __ldcg(&((const float4*)g_dpos)[lane]);
    const float4 dn4 = __ldcg(&((const float4*)g_dneg)[lane]);
    const int4   m4  = __ldcg(&((const int4*)g_mode)[lane]);
    const float4 b34 = ((const float4*)b3)[lane];
    const float  bias0 = bias[0];
    const bool   fast = (m4.x | m4.y | m4.z | m4.w) == 0;
    const int    f0   = lane * 4;

#pragma unroll
    for (int it = 0; it < 8; it++) {
        const int b = blockIdx.x * ROWS_PER_BLOCK + it * 4 + warp;
        const float4 x = in4[b * (NF / 4) + lane];
        float4 c;
        if (fast) {
            c.x = fmaf(x.x, (x.x > 0.f ? dp4.x : dn4.x), b34.x);
            c.y = fmaf(x.y, (x.y > 0.f ? dp4.y : dn4.y), b34.y);
            c.z = fmaf(x.z, (x.z > 0.f ? dp4.z : dn4.z), b34.z);
            c.w = fmaf(x.w, (x.w > 0.f ? dp4.w : dn4.w), b34.w);
        } else {
            c.x = mlp_full(x.x, f0 + 0, W1, b1, W2, b2, W3) + b34.x;
            c.y = mlp_full(x.y, f0 + 1, W1, b1, W2, b2, W3) + b34.y;
            c.z = mlp_full(x.z, f0 + 2, W1, b1, W2, b2, W3) + b34.z;
            c.w = mlp_full(x.w, f0 + 3, W1, b1, W2, b2, W3) + b34.w;
        }
        c4[b * (NF / 4) + lane] = c;

        float s = (c.x + c.y) + (c.z + c.w);
#pragma unroll
        for (int o = 16; o > 0; o >>= 1)
            s += __shfl_xor_sync(0xffffffffu, s, o);
        if (lane == 0) out[b] = s + bias0;
    }

    // ---- Epilogue: reset counters so every graph replay starts clean -----
    __syncthreads();
    if (tid == 0) {
        __threadfence();
        if (atomicAdd(&g_done, 1) == (int)gridDim.x - 1) {
            g_ready = 0;
            g_done  = 0;
            __threadfence();
        }
    }
}

extern "C" void kernel_launch(void* const* d_in, const int* in_sizes, int n_in,
                              void* d_out, int out_size) {
    const float* inputs = (const float*)d_in[0];
    const float* W1     = (const float*)d_in[1];
    const float* b1     = (const float*)d_in[2];
    const float* W2     = (const float*)d_in[3];
    const float* b2     = (const float*)d_in[4];
    const float* W3     = (const float*)d_in[5];
    const float* b3     = (const float*)d_in[6];
    const float* bias   = (const float*)d_in[7];

    nam_fused<<<GRID, NF>>>(inputs, W1, b1, W2, b2, W3, b3, bias, (float*)d_out);
}

// round 3
// speedup vs baseline: 1.4723x; 1.4723x over previous
#include <cuda_runtime.h>

// NAM_42442866819214 — 2 kernels linked by Programmatic Dependent Launch.
//
// Math collapse (per-feature, valid when b1[f,:]==0 && b2[f,:]==0, verified
// at runtime into g_mode[f]):
//   relu(x*w) = x * (x>0 ? max(w,0) : min(w,0))
//   contrib(b,f) = x * (x>0 ? dpos[f] : dneg[f]) + b3[f]
//
// nam_pre : folds W1,W2,W3 -> dpos/dneg (one warp per feature), triggers PDL
//           at entry so nam_main's launch+prefetch overlaps it.
// nam_main: prefetches its input rows into registers BEFORE
//           cudaGridDependencySynchronize(), then applies the 2-scalar
//           piecewise-linear map, writes contribs + per-row sums.

#define NB   8192
#define NF   128
#define NH1  64
#define NH2  32
#define GRID 256            // NB / ROWS_PER_BLOCK
#define ROWS_PER_BLOCK 32   // 4 warps * 8 rows

__device__ float g_dpos[NF];
__device__ float g_dneg[NF];
__device__ int   g_mode[NF];   // 0 = fast path valid (rewritten every launch)

// ---------------------------------------------------------------- precompute
__global__ void __launch_bounds__(32)
nam_pre(const float* __restrict__ W1,
        const float* __restrict__ b1,
        const float* __restrict__ W2,
        const float* __restrict__ b2,
        const float* __restrict__ W3) {
    cudaTriggerProgrammaticLaunchCompletion();   // let nam_main start now

    const int f = blockIdx.x;
    const int k = threadIdx.x;  // H2 unit, 0..31

    int nz = (b1[f * NH1 + k]      != 0.f) |
             (b1[f * NH1 + 32 + k] != 0.f) |
             (b2[f * NH2 + k]      != 0.f);
    unsigned bal = __ballot_sync(0xffffffffu, nz);

    float cp = 0.f, cn = 0.f;
#pragma unroll
    for (int i = 0; i < NH1; i++) {
        float w  = W1[f * NH1 + i];               // warp-uniform
        float w2 = W2[(f * NH1 + i) * NH2 + k];   // coalesced 128B lines
        cp = fmaf(w2, fmaxf(w, 0.f), cp);
        cn = fmaf(w2, fminf(w, 0.f), cn);
    }
    float w3 = W3[f * NH2 + k];
    float dp = w3 * fmaxf(cp, 0.f);   // x>0: relu(x*cp) = x*max(cp,0)
    float dn = w3 * fminf(cn, 0.f);   // x<0: relu(x*cn) = x*min(cn,0)
#pragma unroll
    for (int o = 16; o > 0; o >>= 1) {
        dp += __shfl_xor_sync(0xffffffffu, dp, o);
        dn += __shfl_xor_sync(0xffffffffu, dn, o);
    }
    if (k == 0) {
        g_dpos[f] = dp;
        g_dneg[f] = dn;
        g_mode[f] = bal ? 1 : 0;
    }
}

// ------------------------------------------------------------------ fallback
// Full per-element MLP. Dead unless b1/b2 are nonzero; noinline keeps it off
// the fast path's register budget as much as possible.
__device__ __noinline__ float mlp_full(float x, int f,
                                       const float* __restrict__ W1,
                                       const float* __restrict__ b1,
                                       const float* __restrict__ W2,
                                       const float* __restrict__ b2,
                                       const float* __restrict__ W3) {
    float acc = 0.f;
    for (int k = 0; k < NH2; k++) {
        float a = b2[f * NH2 + k];
        for (int i = 0; i < NH1; i++) {
            float h1 = fmaxf(fmaf(x, W1[f * NH1 + i], b1[f * NH1 + i]), 0.f);
            a = fmaf(h1, W2[(f * NH1 + i) * NH2 + k], a);
        }
        acc = fmaf(fmaxf(a, 0.f), W3[f * NH2 + k], acc);
    }
    return acc;
}

// ---------------------------------------------------------------------- main
__global__ void __launch_bounds__(NF)
nam_main(const float* __restrict__ inputs,
         const float* __restrict__ W1,
         const float* __restrict__ b1,
         const float* __restrict__ W2,
         const float* __restrict__ b2,
         const float* __restrict__ W3,
         const float* __restrict__ b3,
         const float* __restrict__ bias,
         float* __restrict__ out) {
    const int lane = threadIdx.x & 31;
    const int warp = threadIdx.x >> 5;   // 0..3
    const int f0   = lane * 4;

    const float4* in4 = (const float4*)inputs;
    float4*       c4  = (float4*)(out + NB);

    // ---- prefetch input rows (independent of nam_pre) --------------------
    float4 x[8];
#pragma unroll
    for (int it = 0; it < 8; it++) {
        const int b = blockIdx.x * ROWS_PER_BLOCK + it * 4 + warp;
        x[it] = in4[b * (NF / 4) + lane];
    }

    // ---- wait for nam_pre's results to be visible -------------------------
    cudaGridDependencySynchronize();

    const float4 dp4 = ((const float4*)g_dpos)[lane];
    const float4 dn4 = ((const float4*)g_dneg)[lane];
    const int4   m4  = ((const int4*)g_mode)[lane];
    const float4 b34 = ((const float4*)b3)[lane];
    const float  bias0 = bias[0];
    const bool   fast = (m4.x | m4.y | m4.z | m4.w) == 0;

#pragma unroll
    for (int it = 0; it < 8; it++) {
        const int b = blockIdx.x * ROWS_PER_BLOCK + it * 4 + warp;
        float4 c;
        if (fast) {
            c.x = fmaf(x[it].x, (x[it].x > 0.f ? dp4.x : dn4.x), b34.x);
            c.y = fmaf(x[it].y, (x[it].y > 0.f ? dp4.y : dn4.y), b34.y);
            c.z = fmaf(x[it].z, (x[it].z > 0.f ? dp4.z : dn4.z), b34.z);
            c.w = fmaf(x[it].w, (x[it].w > 0.f ? dp4.w : dn4.w), b34.w);
        } else {
            c.x = mlp_full(x[it].x, f0 + 0, W1, b1, W2, b2, W3) + b34.x;
            c.y = mlp_full(x[it].y, f0 + 1, W1, b1, W2, b2, W3) + b34.y;
            c.z = mlp_full(x[it].z, f0 + 2, W1, b1, W2, b2, W3) + b34.z;
            c.w = mlp_full(x[it].w, f0 + 3, W1, b1, W2, b2, W3) + b34.w;
        }
        c4[b * (NF / 4) + lane] = c;

        float s = (c.x + c.y) + (c.z + c.w);
#pragma unroll
        for (int o = 16; o > 0; o >>= 1)
            s += __shfl_xor_sync(0xffffffffu, s, o);
        if (lane == 0) out[b] = s + bias0;
    }
}

// -------------------------------------------------------------------- launch
extern "C" void kernel_launch(void* const* d_in, const int* in_sizes, int n_in,
                              void* d_out, int out_size) {
    const float* inputs = (const float*)d_in[0];
    const float* W1     = (const float*)d_in[1];
    const float* b1     = (const float*)d_in[2];
    const float* W2     = (const float*)d_in[3];
    const float* b2     = (const float*)d_in[4];
    const float* W3     = (const float*)d_in[5];
    const float* b3     = (const float*)d_in[6];
    const float* bias   = (const float*)d_in[7];
    float* out = (float*)d_out;

    nam_pre<<<NF, 32>>>(W1, b1, W2, b2, W3);

    cudaLaunchConfig_t cfg = {};
    cfg.gridDim  = dim3(GRID, 1, 1);
    cfg.blockDim = dim3(NF, 1, 1);
    cfg.dynamicSmemBytes = 0;
    cfg.stream = 0;  // same (legacy default) stream as nam_pre
    cudaLaunchAttribute attr[1];
    attr[0].id = cudaLaunchAttributeProgrammaticStreamSerialization;
    attr[0].val.programmaticStreamSerializationAllowed = 1;
    cfg.attrs = attr;
    cfg.numAttrs = 1;
    cudaLaunchKernelEx(&cfg, nam_main,
                       inputs, W1, b1, W2, b2, W3, b3, bias, out);
}